// round 4
// baseline (speedup 1.0000x reference)
#include <cuda_runtime.h>
#include <math.h>

#define NTOT 65536
#define ETOT 1048576
#define INDIM 64
#define HDIM 128
#define NB 128
#define NPG 512
#define KKEEP 410   // ceil(0.8*512)

// ---------------- device scratch (no allocations allowed) ----------------
__device__ float g_h  [(size_t)NTOT * HDIM];
__device__ float g_hn [(size_t)NTOT * HDIM];
__device__ float g_agg[(size_t)NTOT * HDIM];
__device__ int   g_deg   [NTOT];
__device__ int   g_incl  [NTOT];
__device__ int   g_rowptr[NTOT + 1];
__device__ int   g_fill  [NTOT];
__device__ int   g_col   [ETOT];
__device__ int   g_bsum[256];
__device__ int   g_boff[256];
__device__ float g_t    [NTOT];
__device__ float g_score[NTOT];
__device__ float g_scale[NTOT];
__device__ int   g_kept [NTOT];
__device__ int   g_kdeg [NTOT];
__device__ float g_xs   [NB * 4 * HDIM];   // 65536 floats, laid out as xcat [B][4H]

// ---------------- helpers ----------------
__device__ __forceinline__ float wredf(float v) {
    v += __shfl_xor_sync(0xFFFFFFFFu, v, 16);
    v += __shfl_xor_sync(0xFFFFFFFFu, v, 8);
    v += __shfl_xor_sync(0xFFFFFFFFu, v, 4);
    v += __shfl_xor_sync(0xFFFFFFFFu, v, 2);
    v += __shfl_xor_sync(0xFFFFFFFFu, v, 1);
    return v;
}
__device__ __forceinline__ int wredi(int v) {
    v += __shfl_xor_sync(0xFFFFFFFFu, v, 16);
    v += __shfl_xor_sync(0xFFFFFFFFu, v, 8);
    v += __shfl_xor_sync(0xFFFFFFFFu, v, 4);
    v += __shfl_xor_sync(0xFFFFFFFFu, v, 2);
    v += __shfl_xor_sync(0xFFFFFFFFu, v, 1);
    return v;
}

// ---------------- CSR build ----------------
__global__ void k_init() {               // zero deg histogram + xs accumulator (both 65536)
    int i = blockIdx.x * 256 + threadIdx.x;
    g_deg[i] = 0;
    g_xs[i] = 0.f;
}

__global__ void k_hist(const int* __restrict__ dst) {
    int e = blockIdx.x * 256 + threadIdx.x;
    atomicAdd(&g_deg[dst[e]], 1);
}

__global__ void k_scan1() {              // 256 blocks x 256: block inclusive scans
    __shared__ int s[256];
    int i = blockIdx.x * 256 + threadIdx.x;
    int v = g_deg[i];
    s[threadIdx.x] = v;
    __syncthreads();
    for (int off = 1; off < 256; off <<= 1) {
        int t = (threadIdx.x >= off) ? s[threadIdx.x - off] : 0;
        __syncthreads();
        s[threadIdx.x] += t;
        __syncthreads();
    }
    g_incl[i] = s[threadIdx.x];
    if (threadIdx.x == 255) g_bsum[blockIdx.x] = s[255];
}

__global__ void k_scan2() {              // 1 block: exclusive scan of block sums
    __shared__ int s[256];
    int v = g_bsum[threadIdx.x];
    s[threadIdx.x] = v;
    __syncthreads();
    for (int off = 1; off < 256; off <<= 1) {
        int t = (threadIdx.x >= off) ? s[threadIdx.x - off] : 0;
        __syncthreads();
        s[threadIdx.x] += t;
        __syncthreads();
    }
    g_boff[threadIdx.x] = s[threadIdx.x] - v;   // exclusive
}

__global__ void k_scan3() {
    int i = blockIdx.x * 256 + threadIdx.x;
    int base = g_boff[blockIdx.x];
    int incl = g_incl[i];
    int rp = base + incl - g_deg[i];
    g_rowptr[i] = rp;
    g_fill[i] = rp;
    if (i == NTOT - 1) g_rowptr[NTOT] = base + incl;
}

__global__ void k_scatter(const int* __restrict__ src, const int* __restrict__ dst) {
    int e = blockIdx.x * 256 + threadIdx.x;
    int p = atomicAdd(&g_fill[dst[e]], 1);
    g_col[p] = src[e];
}

// ---------------- SpMM (mean aggregation), warp per node ----------------
__global__ void k_spmm64(const float* __restrict__ xin, float* __restrict__ outp) {
    int node = (blockIdx.x * blockDim.x + threadIdx.x) >> 5;
    if (node >= NTOT) return;
    int lane = threadIdx.x & 31;
    int s = g_rowptr[node], e = g_rowptr[node + 1];
    float ax = 0.f, ay = 0.f;
    int i = s;
    for (; i + 1 < e; i += 2) {
        int s0 = g_col[i], s1 = g_col[i + 1];
        float2 v0 = *((const float2*)(xin + (size_t)s0 * INDIM) + lane);
        float2 v1 = *((const float2*)(xin + (size_t)s1 * INDIM) + lane);
        ax += v0.x; ay += v0.y;
        ax += v1.x; ay += v1.y;
    }
    if (i < e) {
        int s0 = g_col[i];
        float2 v0 = *((const float2*)(xin + (size_t)s0 * INDIM) + lane);
        ax += v0.x; ay += v0.y;
    }
    int c = g_deg[node];
    float inv = 1.f / (float)(c > 1 ? c : 1);
    *((float2*)(outp + (size_t)node * INDIM) + lane) = make_float2(ax * inv, ay * inv);
}

__global__ void k_spmm128(const float* __restrict__ xin, float* __restrict__ outp,
                          const int* __restrict__ cnt) {
    int node = (blockIdx.x * blockDim.x + threadIdx.x) >> 5;
    if (node >= NTOT) return;
    int lane = threadIdx.x & 31;
    int s = g_rowptr[node], e = g_rowptr[node + 1];
    float ax = 0.f, ay = 0.f, az = 0.f, aw = 0.f;
    int i = s;
    for (; i + 1 < e; i += 2) {
        int s0 = g_col[i], s1 = g_col[i + 1];
        float4 v0 = *((const float4*)(xin + (size_t)s0 * HDIM) + lane);
        float4 v1 = *((const float4*)(xin + (size_t)s1 * HDIM) + lane);
        ax += v0.x; ay += v0.y; az += v0.z; aw += v0.w;
        ax += v1.x; ay += v1.y; az += v1.z; aw += v1.w;
    }
    if (i < e) {
        int s0 = g_col[i];
        float4 v0 = *((const float4*)(xin + (size_t)s0 * HDIM) + lane);
        ax += v0.x; ay += v0.y; az += v0.z; aw += v0.w;
    }
    int c = cnt[node];
    float inv = 1.f / (float)(c > 1 ? c : 1);
    *((float4*)(outp + (size_t)node * HDIM) + lane) =
        make_float4(ax * inv, ay * inv, az * inv, aw * inv);
}

// ---------------- fused dual GEMM: C = relu(A1@W1 + A2@W2 + b) * keptMask ----------------
// M = NTOT, N = 128. Tiles: 128x128, BK = 16, 256 threads, 8x8 per thread.
__global__ void __launch_bounds__(256, 2)
k_gemm_dual(const float* __restrict__ A1, int K1, const float* __restrict__ W1,
            const float* __restrict__ A2, int K2, const float* __restrict__ W2,
            const float* __restrict__ bias, const int* __restrict__ keptMask,
            float* __restrict__ C) {
    __shared__ float As[16][132];
    __shared__ float Bs[16][128];
    const int bm = blockIdx.x * 128;
    const int tid = threadIdx.x;
    const int tx = tid & 15;
    const int ty = tid >> 4;

    float acc[8][8];
#pragma unroll
    for (int i = 0; i < 8; i++)
#pragma unroll
        for (int j = 0; j < 8; j++) acc[i][j] = 0.f;

    const int lm  = tid >> 2;          // 0..63
    const int lk  = (tid & 3) << 2;    // 0,4,8,12
    const int ln  = (tid & 31) << 2;   // 0..124
    const int lkw = tid >> 5;          // 0..7

#pragma unroll
    for (int srcSel = 0; srcSel < 2; srcSel++) {
        const float* A = srcSel ? A2 : A1;
        const float* W = srcSel ? W2 : W1;
        const int K = srcSel ? K2 : K1;
        for (int k0 = 0; k0 < K; k0 += 16) {
            float4 a0 = *(const float4*)(A + (size_t)(bm + lm) * K + k0 + lk);
            float4 a1 = *(const float4*)(A + (size_t)(bm + lm + 64) * K + k0 + lk);
            float4 b0 = *(const float4*)(W + (size_t)(k0 + lkw) * HDIM + ln);
            float4 b1 = *(const float4*)(W + (size_t)(k0 + lkw + 8) * HDIM + ln);
            As[lk + 0][lm] = a0.x; As[lk + 1][lm] = a0.y;
            As[lk + 2][lm] = a0.z; As[lk + 3][lm] = a0.w;
            As[lk + 0][lm + 64] = a1.x; As[lk + 1][lm + 64] = a1.y;
            As[lk + 2][lm + 64] = a1.z; As[lk + 3][lm + 64] = a1.w;
            *(float4*)&Bs[lkw][ln] = b0;
            *(float4*)&Bs[lkw + 8][ln] = b1;
            __syncthreads();
#pragma unroll
            for (int k = 0; k < 16; k++) {
                float a[8], b[8];
                *(float4*)&a[0] = *(const float4*)&As[k][ty * 8];
                *(float4*)&a[4] = *(const float4*)&As[k][ty * 8 + 4];
                *(float4*)&b[0] = *(const float4*)&Bs[k][tx * 8];
                *(float4*)&b[4] = *(const float4*)&Bs[k][tx * 8 + 4];
#pragma unroll
                for (int i = 0; i < 8; i++)
#pragma unroll
                    for (int j = 0; j < 8; j++) acc[i][j] += a[i] * b[j];
            }
            __syncthreads();
        }
    }
#pragma unroll
    for (int i = 0; i < 8; i++) {
        int m = bm + ty * 8 + i;
        float km = keptMask ? (keptMask[m] ? 1.f : 0.f) : 1.f;
#pragma unroll
        for (int jj = 0; jj < 8; jj += 4) {
            int n = tx * 8 + jj;
            float4 o;
            o.x = fmaxf(acc[i][jj + 0] + bias[n + 0], 0.f) * km;
            o.y = fmaxf(acc[i][jj + 1] + bias[n + 1], 0.f) * km;
            o.z = fmaxf(acc[i][jj + 2] + bias[n + 2], 0.f) * km;
            o.w = fmaxf(acc[i][jj + 3] + bias[n + 3], 0.f) * km;
            *(float4*)(C + (size_t)m * HDIM + n) = o;
        }
    }
}

// ---------------- global mean pool into xs slot ----------------
__global__ void k_pool(const float* __restrict__ h, int slot, float inv) {
    int g = blockIdx.x, seg = blockIdx.y, c = threadIdx.x;
    const float* base = h + (size_t)(g * NPG + seg * 128) * HDIM + c;
    float acc = 0.f;
#pragma unroll 4
    for (int r = 0; r < 128; r++) acc += base[(size_t)r * HDIM];
    atomicAdd(&g_xs[g * (4 * HDIM) + slot * HDIM + c], acc * inv);
}

// ---------------- SAGPool scoring ----------------
__global__ void k_trel(const float* __restrict__ h, const float* __restrict__ pw_rel) {
    int node = (blockIdx.x * blockDim.x + threadIdx.x) >> 5;
    if (node >= NTOT) return;
    int lane = threadIdx.x & 31;
    float4 hv = *((const float4*)(h + (size_t)node * HDIM) + lane);
    float4 wv = *((const float4*)pw_rel + lane);
    float p = hv.x * wv.x + hv.y * wv.y + hv.z * wv.z + hv.w * wv.w;
    p = wredf(p);
    if (lane == 0) g_t[node] = p;
}

__global__ void k_score(const float* __restrict__ h, const float* __restrict__ pw_root,
                        const float* __restrict__ pb) {
    int node = (blockIdx.x * blockDim.x + threadIdx.x) >> 5;
    if (node >= NTOT) return;
    int lane = threadIdx.x & 31;
    float4 hv = *((const float4*)(h + (size_t)node * HDIM) + lane);
    float4 wv = *((const float4*)pw_root + lane);
    float p = hv.x * wv.x + hv.y * wv.y + hv.z * wv.z + hv.w * wv.w;
    int s = g_rowptr[node], e = g_rowptr[node + 1];
    for (int i = s + lane; i < e; i += 32) p += g_t[g_col[i]];
    p = wredf(p);
    if (lane == 0) g_score[node] = p + pb[0];
}

// exact top-k (k=410 of 512) per graph via rank counting; ties -> lower index (matches lax.top_k)
__global__ void k_topk() {
    __shared__ float s[NPG];
    int g = blockIdx.x, tid = threadIdx.x;
    float v = g_score[g * NPG + tid];
    s[tid] = v;
    __syncthreads();
    int rank = 0;
#pragma unroll 8
    for (int j = 0; j < NPG; j++) {
        float o = s[j];
        rank += (o > v) || (o == v && j < tid);
    }
    int keep = rank < KKEEP;
    g_kept[g * NPG + tid] = keep;
    g_scale[g * NPG + tid] = keep ? tanhf(v) : 0.f;
}

__global__ void k_apply(float* __restrict__ h) {   // h *= scale (zeros dropped rows)
    int i = blockIdx.x * blockDim.x + threadIdx.x;  // NTOT*32 float4s
    int node = i >> 5;
    float sc = g_scale[node];
    float4* p = (float4*)h + i;
    float4 v = *p;
    v.x *= sc; v.y *= sc; v.z *= sc; v.w *= sc;
    *p = v;
}

__global__ void k_kdeg() {   // kept-source in-degree per node
    int node = (blockIdx.x * blockDim.x + threadIdx.x) >> 5;
    if (node >= NTOT) return;
    int lane = threadIdx.x & 31;
    int s = g_rowptr[node], e = g_rowptr[node + 1];
    int c = 0;
    for (int i = s + lane; i < e; i += 32) c += g_kept[g_col[i]];
    c = wredi(c);
    if (lane == 0) g_kdeg[node] = c;
}

// ---------------- MLP head + log_softmax, block per graph ----------------
__global__ void k_mlp(const float* __restrict__ lin1W, const float* __restrict__ lin1b,
                      const float* __restrict__ lin2W, const float* __restrict__ lin2b,
                      float* __restrict__ out) {
    __shared__ float sx[512];
    __shared__ float r0[128], r1[128];
    int g = blockIdx.x, tid = threadIdx.x;
    for (int i = tid; i < 512; i += 128) sx[i] = g_xs[g * 512 + i];
    __syncthreads();
    float acc = lin1b[tid];
#pragma unroll 8
    for (int k = 0; k < 512; k++) acc += sx[k] * lin1W[k * 128 + tid];
    float hval = fmaxf(acc, 0.f);
    r0[tid] = hval * lin2W[tid * 2 + 0];
    r1[tid] = hval * lin2W[tid * 2 + 1];
    __syncthreads();
    for (int off = 64; off > 0; off >>= 1) {
        if (tid < off) { r0[tid] += r0[tid + off]; r1[tid] += r1[tid + off]; }
        __syncthreads();
    }
    if (tid == 0) {
        float z0 = r0[0] + lin2b[0], z1 = r1[0] + lin2b[1];
        float m = fmaxf(z0, z1);
        float l = m + logf(expf(z0 - m) + expf(z1 - m));
        out[g * 2 + 0] = z0 - l;
        out[g * 2 + 1] = z1 - l;
    }
}

// ---------------- launcher ----------------
extern "C" void kernel_launch(void* const* d_in, const int* in_sizes, int n_in,
                              void* d_out, int out_size) {
    const float* x       = (const float*)d_in[0];
    const int*   ei      = (const int*)  d_in[1];
    const float* W1_rel  = (const float*)d_in[3];
    const float* W1_root = (const float*)d_in[4];
    const float* b1      = (const float*)d_in[5];
    const float* Wc_rel  = (const float*)d_in[6];
    const float* Wc_root = (const float*)d_in[7];
    const float* bc      = (const float*)d_in[8];
    const float* pw_rel  = (const float*)d_in[9];
    const float* pw_root = (const float*)d_in[10];
    const float* pb      = (const float*)d_in[11];
    const float* lin1W   = (const float*)d_in[12];
    const float* lin1b   = (const float*)d_in[13];
    const float* lin2W   = (const float*)d_in[14];
    const float* lin2b   = (const float*)d_in[15];
    float* out = (float*)d_out;

    const int* srcp = ei;
    const int* dstp = ei + ETOT;

    float *hA, *hB, *agg;
    int *degp, *kdegp, *keptp;
    cudaGetSymbolAddress((void**)&hA,    g_h);
    cudaGetSymbolAddress((void**)&hB,    g_hn);
    cudaGetSymbolAddress((void**)&agg,   g_agg);
    cudaGetSymbolAddress((void**)&degp,  g_deg);
    cudaGetSymbolAddress((void**)&kdegp, g_kdeg);
    cudaGetSymbolAddress((void**)&keptp, g_kept);

    // CSR build (by dst)
    k_init   <<<NTOT / 256, 256>>>();
    k_hist   <<<ETOT / 256, 256>>>(dstp);
    k_scan1  <<<256, 256>>>();
    k_scan2  <<<1, 256>>>();
    k_scan3  <<<256, 256>>>();
    k_scatter<<<ETOT / 256, 256>>>(srcp, dstp);

    // conv1 (IN=64 -> H)
    k_spmm64   <<<8192, 256>>>(x, agg);
    k_gemm_dual<<<512, 256>>>(agg, 64, W1_rel, x, 64, W1_root, b1, nullptr, hA);
    k_pool     <<<dim3(NB, 4), 128>>>(hA, 0, 1.f / (float)NPG);

    // convs[0]
    k_spmm128  <<<8192, 256>>>(hA, agg, degp);
    k_gemm_dual<<<512, 256>>>(agg, 128, Wc_rel, hA, 128, Wc_root, bc, nullptr, hB);
    k_pool     <<<dim3(NB, 4), 128>>>(hB, 1, 1.f / (float)NPG);

    // SAGPool (score via GraphConv(H,1), aggr=add)
    k_trel <<<8192, 256>>>(hB, pw_rel);
    k_score<<<8192, 256>>>(hB, pw_root, pb);
    k_topk <<<NB, NPG>>>();
    k_apply<<<8192, 256>>>(hB);
    k_kdeg <<<8192, 256>>>();

    // convs[1]
    k_spmm128  <<<8192, 256>>>(hB, agg, kdegp);
    k_gemm_dual<<<512, 256>>>(agg, 128, Wc_rel + HDIM * HDIM, hB, 128,
                              Wc_root + HDIM * HDIM, bc + HDIM, keptp, hA);
    k_pool     <<<dim3(NB, 4), 128>>>(hA, 2, 1.f / (float)KKEEP);

    // convs[2]
    k_spmm128  <<<8192, 256>>>(hA, agg, kdegp);
    k_gemm_dual<<<512, 256>>>(agg, 128, Wc_rel + 2 * HDIM * HDIM, hA, 128,
                              Wc_root + 2 * HDIM * HDIM, bc + 2 * HDIM, keptp, hB);
    k_pool     <<<dim3(NB, 4), 128>>>(hB, 3, 1.f / (float)KKEEP);

    // MLP head + log_softmax
    k_mlp<<<NB, 128>>>(lin1W, lin1b, lin2W, lin2b, out);
}

// round 5
// speedup vs baseline: 1.3309x; 1.3309x over previous
#include <cuda_runtime.h>
#include <cuda_bf16.h>
#include <math.h>

#define NTOT 65536
#define ETOT 1048576
#define INDIM 64
#define HDIM 128
#define NB 128
#define NPG 512
#define KKEEP 410   // ceil(0.8*512)

// ---------------- device scratch (no allocations allowed) ----------------
__device__ float g_h  [(size_t)NTOT * HDIM];
__device__ float g_hn [(size_t)NTOT * HDIM];
__device__ float g_agg[(size_t)NTOT * HDIM];
__device__ int   g_deg   [NTOT];
__device__ int   g_incl  [NTOT];
__device__ int   g_rowptr[NTOT + 1];
__device__ int   g_fill  [NTOT];
__device__ int   g_col   [ETOT];
__device__ int   g_bsum[256];
__device__ int   g_boff[256];
__device__ float g_t    [NTOT];
__device__ float g_score[NTOT];
__device__ float g_scale[NTOT];
__device__ int   g_kept [NTOT];
__device__ int   g_kdeg [NTOT];
__device__ float g_xs   [NB * 4 * HDIM];   // xcat [B][4H]

// bf16 hi/lo transposed weights: 8 slots of [N=128][K<=128]
__device__ unsigned short g_whi[8 * 128 * 128];
__device__ unsigned short g_wlo[8 * 128 * 128];

// ---------------- helpers ----------------
__device__ __forceinline__ float wredf(float v) {
    v += __shfl_xor_sync(0xFFFFFFFFu, v, 16);
    v += __shfl_xor_sync(0xFFFFFFFFu, v, 8);
    v += __shfl_xor_sync(0xFFFFFFFFu, v, 4);
    v += __shfl_xor_sync(0xFFFFFFFFu, v, 2);
    v += __shfl_xor_sync(0xFFFFFFFFu, v, 1);
    return v;
}
__device__ __forceinline__ int wredi(int v) {
    v += __shfl_xor_sync(0xFFFFFFFFu, v, 16);
    v += __shfl_xor_sync(0xFFFFFFFFu, v, 8);
    v += __shfl_xor_sync(0xFFFFFFFFu, v, 4);
    v += __shfl_xor_sync(0xFFFFFFFFu, v, 2);
    v += __shfl_xor_sync(0xFFFFFFFFu, v, 1);
    return v;
}

// ---------------- CSR build ----------------
__global__ void k_init() {
    int i = blockIdx.x * 256 + threadIdx.x;
    g_deg[i] = 0;
    g_xs[i] = 0.f;
}

__global__ void k_hist(const int* __restrict__ dst) {
    int e = blockIdx.x * 256 + threadIdx.x;
    atomicAdd(&g_deg[dst[e]], 1);
}

__global__ void k_scan1() {
    __shared__ int s[256];
    int i = blockIdx.x * 256 + threadIdx.x;
    int v = g_deg[i];
    s[threadIdx.x] = v;
    __syncthreads();
    for (int off = 1; off < 256; off <<= 1) {
        int t = (threadIdx.x >= off) ? s[threadIdx.x - off] : 0;
        __syncthreads();
        s[threadIdx.x] += t;
        __syncthreads();
    }
    g_incl[i] = s[threadIdx.x];
    if (threadIdx.x == 255) g_bsum[blockIdx.x] = s[255];
}

__global__ void k_scan2() {
    __shared__ int s[256];
    int v = g_bsum[threadIdx.x];
    s[threadIdx.x] = v;
    __syncthreads();
    for (int off = 1; off < 256; off <<= 1) {
        int t = (threadIdx.x >= off) ? s[threadIdx.x - off] : 0;
        __syncthreads();
        s[threadIdx.x] += t;
        __syncthreads();
    }
    g_boff[threadIdx.x] = s[threadIdx.x] - v;
}

__global__ void k_scan3() {
    int i = blockIdx.x * 256 + threadIdx.x;
    int base = g_boff[blockIdx.x];
    int incl = g_incl[i];
    int rp = base + incl - g_deg[i];
    g_rowptr[i] = rp;
    g_fill[i] = rp;
    if (i == NTOT - 1) g_rowptr[NTOT] = base + incl;
}

__global__ void k_scatter(const int* __restrict__ src, const int* __restrict__ dst) {
    int e = blockIdx.x * 256 + threadIdx.x;
    int p = atomicAdd(&g_fill[dst[e]], 1);
    g_col[p] = src[e];
}

// ---------------- weight prep: fp32 [K][128] -> bf16 hi/lo transposed [128][K] ----------------
__global__ void k_prepw(const float* __restrict__ W, int K, int slot, int slotStride) {
    int z = blockIdx.z;                         // matrix index
    const float* Ws = W + (size_t)z * K * 128;
    unsigned short* oh = g_whi + (size_t)(slot + z * slotStride) * 16384;
    unsigned short* ol = g_wlo + (size_t)(slot + z * slotStride) * 16384;
    int idx = blockIdx.x * 256 + threadIdx.x;   // idx over K*128 outputs
    if (idx >= K * 128) return;
    int n = idx / K, k = idx % K;
    float v = Ws[(size_t)k * 128 + n];
    __nv_bfloat16 h = __float2bfloat16_rn(v);
    __nv_bfloat16 l = __float2bfloat16_rn(v - __bfloat162float(h));
    oh[idx] = __bfloat16_as_ushort(h);
    ol[idx] = __bfloat16_as_ushort(l);
}

// ---------------- SpMM (mean aggregation), warp per node ----------------
__global__ void k_spmm64(const float* __restrict__ xin, float* __restrict__ outp) {
    int node = (blockIdx.x * blockDim.x + threadIdx.x) >> 5;
    if (node >= NTOT) return;
    int lane = threadIdx.x & 31;
    int s = g_rowptr[node], e = g_rowptr[node + 1];
    float ax = 0.f, ay = 0.f;
    int i = s;
    for (; i + 1 < e; i += 2) {
        int s0 = g_col[i], s1 = g_col[i + 1];
        float2 v0 = *((const float2*)(xin + (size_t)s0 * INDIM) + lane);
        float2 v1 = *((const float2*)(xin + (size_t)s1 * INDIM) + lane);
        ax += v0.x; ay += v0.y;
        ax += v1.x; ay += v1.y;
    }
    if (i < e) {
        int s0 = g_col[i];
        float2 v0 = *((const float2*)(xin + (size_t)s0 * INDIM) + lane);
        ax += v0.x; ay += v0.y;
    }
    int c = g_deg[node];
    float inv = 1.f / (float)(c > 1 ? c : 1);
    *((float2*)(outp + (size_t)node * INDIM) + lane) = make_float2(ax * inv, ay * inv);
}

__global__ void k_spmm128(const float* __restrict__ xin, float* __restrict__ outp,
                          const int* __restrict__ cnt) {
    int node = (blockIdx.x * blockDim.x + threadIdx.x) >> 5;
    if (node >= NTOT) return;
    int lane = threadIdx.x & 31;
    int s = g_rowptr[node], e = g_rowptr[node + 1];
    float ax = 0.f, ay = 0.f, az = 0.f, aw = 0.f;
    int i = s;
    for (; i + 1 < e; i += 2) {
        int s0 = g_col[i], s1 = g_col[i + 1];
        float4 v0 = *((const float4*)(xin + (size_t)s0 * HDIM) + lane);
        float4 v1 = *((const float4*)(xin + (size_t)s1 * HDIM) + lane);
        ax += v0.x; ay += v0.y; az += v0.z; aw += v0.w;
        ax += v1.x; ay += v1.y; az += v1.z; aw += v1.w;
    }
    if (i < e) {
        int s0 = g_col[i];
        float4 v0 = *((const float4*)(xin + (size_t)s0 * HDIM) + lane);
        ax += v0.x; ay += v0.y; az += v0.z; aw += v0.w;
    }
    int c = cnt[node];
    float inv = 1.f / (float)(c > 1 ? c : 1);
    *((float4*)(outp + (size_t)node * HDIM) + lane) =
        make_float4(ax * inv, ay * inv, az * inv, aw * inv);
}

// ---------------- tensor-core dual GEMM ----------------
// C[m,128] = relu(A1@W1 + A2@W2 + b) * keptMask, bf16 hi/lo split, fp32 accumulate.
// Block 128x128, 8 warps; warp tile 32x64. Smem stride 24 bf16 (bank-conflict-free).

#define AS_STR 24

__device__ __forceinline__ void mma16816(float* d, const unsigned* a, unsigned b0, unsigned b1) {
    asm volatile(
        "mma.sync.aligned.m16n8k16.row.col.f32.bf16.bf16.f32 "
        "{%0,%1,%2,%3}, {%4,%5,%6,%7}, {%8,%9}, {%0,%1,%2,%3};\n"
        : "+f"(d[0]), "+f"(d[1]), "+f"(d[2]), "+f"(d[3])
        : "r"(a[0]), "r"(a[1]), "r"(a[2]), "r"(a[3]), "r"(b0), "r"(b1));
}

__device__ __forceinline__ unsigned pack2(float x, float y, unsigned& lo) {
    __nv_bfloat16 hx = __float2bfloat16_rn(x);
    __nv_bfloat16 hy = __float2bfloat16_rn(y);
    __nv_bfloat16 lx = __float2bfloat16_rn(x - __bfloat162float(hx));
    __nv_bfloat16 ly = __float2bfloat16_rn(y - __bfloat162float(hy));
    lo = (unsigned)__bfloat16_as_ushort(lx) | ((unsigned)__bfloat16_as_ushort(ly) << 16);
    return (unsigned)__bfloat16_as_ushort(hx) | ((unsigned)__bfloat16_as_ushort(hy) << 16);
}

__global__ void __launch_bounds__(256, 2)
k_gemm_tc(const float* __restrict__ A1, int K1, int slot1,
          const float* __restrict__ A2, int K2, int slot2,
          const float* __restrict__ bias, const int* __restrict__ keptMask,
          float* __restrict__ C) {
    __shared__ __align__(16) unsigned short As_hi[128 * AS_STR];
    __shared__ __align__(16) unsigned short As_lo[128 * AS_STR];
    __shared__ __align__(16) unsigned short Bs_hi[128 * AS_STR];
    __shared__ __align__(16) unsigned short Bs_lo[128 * AS_STR];

    const int tid = threadIdx.x, wid = tid >> 5, lane = tid & 31;
    const int wm = (wid & 3) * 32;        // warp m offset within block
    const int wn = (wid >> 2) * 64;       // warp n offset within block
    const int groupID = lane >> 2, tig = lane & 3;
    const int bm = blockIdx.x * 128;

    // staging indices
    const int sr = tid >> 1;              // row 0..127
    const int sc = (tid & 1) * 8;         // col 0 or 8

    float acc[2][8][4];
#pragma unroll
    for (int mt = 0; mt < 2; mt++)
#pragma unroll
        for (int nt = 0; nt < 8; nt++)
#pragma unroll
            for (int j = 0; j < 4; j++) acc[mt][nt][j] = 0.f;

#pragma unroll
    for (int srcSel = 0; srcSel < 2; srcSel++) {
        const float* A = srcSel ? A2 : A1;
        const int K = srcSel ? K2 : K1;
        const unsigned short* Wh = g_whi + (size_t)(srcSel ? slot2 : slot1) * 16384;
        const unsigned short* Wl = g_wlo + (size_t)(srcSel ? slot2 : slot1) * 16384;

        for (int k0 = 0; k0 < K; k0 += 16) {
            // ---- stage A (fp32 -> bf16 hi/lo) ----
            const float* ap = A + (size_t)(bm + sr) * K + k0 + sc;
            float4 f0 = *(const float4*)ap;
            float4 f1 = *(const float4*)(ap + 4);
            unsigned l0, l1, l2, l3;
            unsigned h0 = pack2(f0.x, f0.y, l0);
            unsigned h1 = pack2(f0.z, f0.w, l1);
            unsigned h2 = pack2(f1.x, f1.y, l2);
            unsigned h3 = pack2(f1.z, f1.w, l3);
            *(uint4*)&As_hi[sr * AS_STR + sc] = make_uint4(h0, h1, h2, h3);
            *(uint4*)&As_lo[sr * AS_STR + sc] = make_uint4(l0, l1, l2, l3);
            // ---- stage W (already bf16, [n][K]) ----
            uint4 wh = *(const uint4*)(Wh + (size_t)sr * K + k0 + sc);
            uint4 wl = *(const uint4*)(Wl + (size_t)sr * K + k0 + sc);
            *(uint4*)&Bs_hi[sr * AS_STR + sc] = wh;
            *(uint4*)&Bs_lo[sr * AS_STR + sc] = wl;
            __syncthreads();

            // ---- A fragments ----
            unsigned ah[2][4], al[2][4];
#pragma unroll
            for (int mt = 0; mt < 2; mt++) {
                int m0 = wm + mt * 16 + groupID;
                const unsigned short* p = &As_hi[m0 * AS_STR + 2 * tig];
                ah[mt][0] = *(const unsigned*)p;
                ah[mt][1] = *(const unsigned*)(p + 8 * AS_STR);
                ah[mt][2] = *(const unsigned*)(p + 8);
                ah[mt][3] = *(const unsigned*)(p + 8 * AS_STR + 8);
                const unsigned short* q = &As_lo[m0 * AS_STR + 2 * tig];
                al[mt][0] = *(const unsigned*)q;
                al[mt][1] = *(const unsigned*)(q + 8 * AS_STR);
                al[mt][2] = *(const unsigned*)(q + 8);
                al[mt][3] = *(const unsigned*)(q + 8 * AS_STR + 8);
            }
            // ---- B fragments + MMA ----
#pragma unroll
            for (int nt = 0; nt < 8; nt++) {
                int n0 = (wn + nt * 8 + groupID) * AS_STR + 2 * tig;
                unsigned bh0 = *(const unsigned*)&Bs_hi[n0];
                unsigned bh1 = *(const unsigned*)&Bs_hi[n0 + 8];
                unsigned bl0 = *(const unsigned*)&Bs_lo[n0];
                unsigned bl1 = *(const unsigned*)&Bs_lo[n0 + 8];
#pragma unroll
                for (int mt = 0; mt < 2; mt++) {
                    mma16816(acc[mt][nt], ah[mt], bh0, bh1);
                    mma16816(acc[mt][nt], ah[mt], bl0, bl1);
                    mma16816(acc[mt][nt], al[mt], bh0, bh1);
                }
            }
            __syncthreads();
        }
    }

    // ---- epilogue: bias + relu + mask ----
#pragma unroll
    for (int mt = 0; mt < 2; mt++) {
        int r0 = bm + wm + mt * 16 + groupID;
        int r1 = r0 + 8;
        float km0 = keptMask ? (keptMask[r0] ? 1.f : 0.f) : 1.f;
        float km1 = keptMask ? (keptMask[r1] ? 1.f : 0.f) : 1.f;
#pragma unroll
        for (int nt = 0; nt < 8; nt++) {
            int n = wn + nt * 8 + 2 * tig;
            float b0 = bias[n], b1 = bias[n + 1];
            float2 o0, o1;
            o0.x = fmaxf(acc[mt][nt][0] + b0, 0.f) * km0;
            o0.y = fmaxf(acc[mt][nt][1] + b1, 0.f) * km0;
            o1.x = fmaxf(acc[mt][nt][2] + b0, 0.f) * km1;
            o1.y = fmaxf(acc[mt][nt][3] + b1, 0.f) * km1;
            *(float2*)(C + (size_t)r0 * HDIM + n) = o0;
            *(float2*)(C + (size_t)r1 * HDIM + n) = o1;
        }
    }
}

// ---------------- global mean pool into xs slot ----------------
__global__ void k_pool(const float* __restrict__ h, int slot, float inv) {
    int g = blockIdx.x, seg = blockIdx.y, c = threadIdx.x;
    const float* base = h + (size_t)(g * NPG + seg * 128) * HDIM + c;
    float acc = 0.f;
#pragma unroll 4
    for (int r = 0; r < 128; r++) acc += base[(size_t)r * HDIM];
    atomicAdd(&g_xs[g * (4 * HDIM) + slot * HDIM + c], acc * inv);
}

// ---------------- SAGPool scoring ----------------
__global__ void k_trel(const float* __restrict__ h, const float* __restrict__ pw_rel) {
    int node = (blockIdx.x * blockDim.x + threadIdx.x) >> 5;
    if (node >= NTOT) return;
    int lane = threadIdx.x & 31;
    float4 hv = *((const float4*)(h + (size_t)node * HDIM) + lane);
    float4 wv = *((const float4*)pw_rel + lane);
    float p = hv.x * wv.x + hv.y * wv.y + hv.z * wv.z + hv.w * wv.w;
    p = wredf(p);
    if (lane == 0) g_t[node] = p;
}

__global__ void k_score(const float* __restrict__ h, const float* __restrict__ pw_root,
                        const float* __restrict__ pb) {
    int node = (blockIdx.x * blockDim.x + threadIdx.x) >> 5;
    if (node >= NTOT) return;
    int lane = threadIdx.x & 31;
    float4 hv = *((const float4*)(h + (size_t)node * HDIM) + lane);
    float4 wv = *((const float4*)pw_root + lane);
    float p = hv.x * wv.x + hv.y * wv.y + hv.z * wv.z + hv.w * wv.w;
    int s = g_rowptr[node], e = g_rowptr[node + 1];
    for (int i = s + lane; i < e; i += 32) p += g_t[g_col[i]];
    p = wredf(p);
    if (lane == 0) g_score[node] = p + pb[0];
}

// exact top-k (k=410 of 512) per graph via rank counting; ties -> lower index
__global__ void k_topk() {
    __shared__ float s[NPG];
    int g = blockIdx.x, tid = threadIdx.x;
    float v = g_score[g * NPG + tid];
    s[tid] = v;
    __syncthreads();
    int rank = 0;
#pragma unroll 8
    for (int j = 0; j < NPG; j++) {
        float o = s[j];
        rank += (o > v) || (o == v && j < tid);
    }
    int keep = rank < KKEEP;
    g_kept[g * NPG + tid] = keep;
    g_scale[g * NPG + tid] = keep ? tanhf(v) : 0.f;
}

__global__ void k_apply(float* __restrict__ h) {
    int i = blockIdx.x * blockDim.x + threadIdx.x;
    int node = i >> 5;
    float sc = g_scale[node];
    float4* p = (float4*)h + i;
    float4 v = *p;
    v.x *= sc; v.y *= sc; v.z *= sc; v.w *= sc;
    *p = v;
}

__global__ void k_kdeg() {
    int node = (blockIdx.x * blockDim.x + threadIdx.x) >> 5;
    if (node >= NTOT) return;
    int lane = threadIdx.x & 31;
    int s = g_rowptr[node], e = g_rowptr[node + 1];
    int c = 0;
    for (int i = s + lane; i < e; i += 32) c += g_kept[g_col[i]];
    c = wredi(c);
    if (lane == 0) g_kdeg[node] = c;
}

// ---------------- MLP head + log_softmax, block per graph ----------------
__global__ void k_mlp(const float* __restrict__ lin1W, const float* __restrict__ lin1b,
                      const float* __restrict__ lin2W, const float* __restrict__ lin2b,
                      float* __restrict__ out) {
    __shared__ float sx[512];
    __shared__ float r0[128], r1[128];
    int g = blockIdx.x, tid = threadIdx.x;
    for (int i = tid; i < 512; i += 128) sx[i] = g_xs[g * 512 + i];
    __syncthreads();
    float acc = lin1b[tid];
#pragma unroll 8
    for (int k = 0; k < 512; k++) acc += sx[k] * lin1W[k * 128 + tid];
    float hval = fmaxf(acc, 0.f);
    r0[tid] = hval * lin2W[tid * 2 + 0];
    r1[tid] = hval * lin2W[tid * 2 + 1];
    __syncthreads();
    for (int off = 64; off > 0; off >>= 1) {
        if (tid < off) { r0[tid] += r0[tid + off]; r1[tid] += r1[tid + off]; }
        __syncthreads();
    }
    if (tid == 0) {
        float z0 = r0[0] + lin2b[0], z1 = r1[0] + lin2b[1];
        float m = fmaxf(z0, z1);
        float l = m + logf(expf(z0 - m) + expf(z1 - m));
        out[g * 2 + 0] = z0 - l;
        out[g * 2 + 1] = z1 - l;
    }
}

// ---------------- launcher ----------------
extern "C" void kernel_launch(void* const* d_in, const int* in_sizes, int n_in,
                              void* d_out, int out_size) {
    const float* x       = (const float*)d_in[0];
    const int*   ei      = (const int*)  d_in[1];
    const float* W1_rel  = (const float*)d_in[3];
    const float* W1_root = (const float*)d_in[4];
    const float* b1      = (const float*)d_in[5];
    const float* Wc_rel  = (const float*)d_in[6];
    const float* Wc_root = (const float*)d_in[7];
    const float* bc      = (const float*)d_in[8];
    const float* pw_rel  = (const float*)d_in[9];
    const float* pw_root = (const float*)d_in[10];
    const float* pb      = (const float*)d_in[11];
    const float* lin1W   = (const float*)d_in[12];
    const float* lin1b   = (const float*)d_in[13];
    const float* lin2W   = (const float*)d_in[14];
    const float* lin2b   = (const float*)d_in[15];
    float* out = (float*)d_out;

    const int* srcp = ei;
    const int* dstp = ei + ETOT;

    float *hA, *hB, *agg;
    int *degp, *kdegp, *keptp;
    cudaGetSymbolAddress((void**)&hA,    g_h);
    cudaGetSymbolAddress((void**)&hB,    g_hn);
    cudaGetSymbolAddress((void**)&agg,   g_agg);
    cudaGetSymbolAddress((void**)&degp,  g_deg);
    cudaGetSymbolAddress((void**)&kdegp, g_kdeg);
    cudaGetSymbolAddress((void**)&keptp, g_kept);

    // CSR build (by dst) + weight prep (independent; overlap in-stream order)
    k_init   <<<NTOT / 256, 256>>>();
    k_prepw  <<<dim3(32, 1, 1), 256>>>(W1_rel, 64, 0, 1);    // slot 0
    k_prepw  <<<dim3(32, 1, 1), 256>>>(W1_root, 64, 1, 1);   // slot 1
    k_prepw  <<<dim3(64, 1, 3), 256>>>(Wc_rel, 128, 2, 2);   // slots 2,4,6
    k_prepw  <<<dim3(64, 1, 3), 256>>>(Wc_root, 128, 3, 2);  // slots 3,5,7
    k_hist   <<<ETOT / 256, 256>>>(dstp);
    k_scan1  <<<256, 256>>>();
    k_scan2  <<<1, 256>>>();
    k_scan3  <<<256, 256>>>();
    k_scatter<<<ETOT / 256, 256>>>(srcp, dstp);

    // conv1 (IN=64 -> H)
    k_spmm64 <<<8192, 256>>>(x, agg);
    k_gemm_tc<<<512, 256>>>(agg, 64, 0, x, 64, 1, b1, nullptr, hA);
    k_pool   <<<dim3(NB, 4), 128>>>(hA, 0, 1.f / (float)NPG);

    // convs[0]
    k_spmm128<<<8192, 256>>>(hA, agg, degp);
    k_gemm_tc<<<512, 256>>>(agg, 128, 2, hA, 128, 3, bc, nullptr, hB);
    k_pool   <<<dim3(NB, 4), 128>>>(hB, 1, 1.f / (float)NPG);

    // SAGPool (score via GraphConv(H,1), aggr=add)
    k_trel <<<8192, 256>>>(hB, pw_rel);
    k_score<<<8192, 256>>>(hB, pw_root, pb);
    k_topk <<<NB, NPG>>>();
    k_apply<<<8192, 256>>>(hB);
    k_kdeg <<<8192, 256>>>();

    // convs[1]
    k_spmm128<<<8192, 256>>>(hB, agg, kdegp);
    k_gemm_tc<<<512, 256>>>(agg, 128, 4, hB, 128, 5, bc + HDIM, keptp, hA);
    k_pool   <<<dim3(NB, 4), 128>>>(hA, 2, 1.f / (float)KKEEP);

    // convs[2]
    k_spmm128<<<8192, 256>>>(hA, agg, kdegp);
    k_gemm_tc<<<512, 256>>>(agg, 128, 6, hA, 128, 7, bc + 2 * HDIM, keptp, hB);
    k_pool   <<<dim3(NB, 4), 128>>>(hB, 3, 1.f / (float)KKEEP);

    // MLP head + log_softmax
    k_mlp<<<NB, 128>>>(lin1W, lin1b, lin2W, lin2b, out);
}